// round 4
// baseline (speedup 1.0000x reference)
#include <cuda_runtime.h>
#include <cuda_bf16.h>
#include <math.h>

// Laplace diagonal recurrence:
//   out[t, i, f] = e[i] * out[t-1, i, f] + decay[i] * inp[t, f]
// T = 2048, N_S = 108, F = 256, fp32.
//
// R4: R3 structure (depth-8 register pipeline, float4, scaled recurrence,
// GI=6) with 2x the concurrency: CHUNK 128->64 => 576 blocks (~16 warps/SM),
// plus streaming stores (__stcs) so the 226 MB write-once output doesn't
// evict the L2-resident input.

constexpr int T_LEN  = 2048;
constexpr int F      = 256;
constexpr int NS     = 108;
constexpr int CHUNK  = 64;
constexpr int WARM   = 64;
constexpr int NCHUNK = T_LEN / CHUNK;   // 32
constexpr int GI     = 6;               // i-values per block
constexpr int NIB    = NS / GI;         // 18
constexpr int PF     = 8;               // prefetch depth (rows)
constexpr int F4     = F / 4;           // 64 float4 lanes per row

__global__ __launch_bounds__(128)
void laplace_kernel(const float* __restrict__ inp, float* __restrict__ out) {
    const int tid = threadIdx.x;
    const int fq  = tid & 63;        // float4 lane: f = 4*fq
    const int iq  = tid >> 6;        // 0..1 -> which half of the 6 i's
    const int ib  = blockIdx.x;      // 0..17
    const int chunk = blockIdx.y;    // 0..31

    // Per-i constants in double precision (matches reference ~1e-7).
    float e[3], dcy[3];
    const double c = pow(20.0, 1.0 / 99.0) - 1.0;
    #pragma unroll
    for (int k = 0; k < 3; k++) {
        int i = ib * GI + iq * 3 + k;
        double tau = pow(1.0 + c, (double)(i - 4));
        double s   = 4.0 / tau;
        double ed  = exp(-s);
        e[k]   = (float)ed;
        dcy[k] = (float)((1.0 - ed) / s);
    }

    const int t_start = chunk * CHUNK;
    const int warm    = (t_start < WARM) ? t_start : WARM;  // 0 or 64
    const int t0      = t_start - warm;
    const int steps   = warm + CHUNK;                        // 64 or 128

    const float4* __restrict__ ip = reinterpret_cast<const float4*>(inp)
                                    + (size_t)t0 * F4 + fq;
    float4* __restrict__ oq = reinterpret_cast<float4*>(out);

    // Scaled states: st' = e*st' + x;  out = dcy * st'.
    float4 st[3];
    #pragma unroll
    for (int k = 0; k < 3; k++) st[k] = make_float4(0.f, 0.f, 0.f, 0.f);

    // Prime the register pipeline.
    float4 pf[PF];
    #pragma unroll
    for (int j = 0; j < PF; j++) pf[j] = __ldg(ip + j * F4);

    // ---- warm-up (no stores), warm is 0 or 64, divisible by PF ----
    for (int tb = 0; tb < warm; tb += PF) {
        #pragma unroll
        for (int j = 0; j < PF; j++) {
            const int t  = tb + j;
            const float4 x = pf[j];
            const int tn = t + PF;
            if (tn < steps) pf[j] = __ldg(ip + (size_t)tn * F4);
            #pragma unroll
            for (int k = 0; k < 3; k++) {
                st[k].x = fmaf(e[k], st[k].x, x.x);
                st[k].y = fmaf(e[k], st[k].y, x.y);
                st[k].z = fmaf(e[k], st[k].z, x.z);
                st[k].w = fmaf(e[k], st[k].w, x.w);
            }
        }
    }

    // ---- main: CHUNK=64 stored rows ----
    // out float4 index: ((t_start+tr)*NS + i)*F4 + fq
    size_t obase = ((size_t)t_start * NS + (size_t)(ib * GI + iq * 3)) * F4 + fq;
    for (int tb = 0; tb < CHUNK; tb += PF) {
        #pragma unroll
        for (int j = 0; j < PF; j++) {
            const int tr = tb + j;          // 0..63
            const int t  = warm + tr;
            const float4 x = pf[j];
            const int tn = t + PF;
            if (tn < steps) pf[j] = __ldg(ip + (size_t)tn * F4);
            #pragma unroll
            for (int k = 0; k < 3; k++) {
                st[k].x = fmaf(e[k], st[k].x, x.x);
                st[k].y = fmaf(e[k], st[k].y, x.y);
                st[k].z = fmaf(e[k], st[k].z, x.z);
                st[k].w = fmaf(e[k], st[k].w, x.w);
                float4 o;
                o.x = dcy[k] * st[k].x;
                o.y = dcy[k] * st[k].y;
                o.z = dcy[k] * st[k].z;
                o.w = dcy[k] * st[k].w;
                __stcs(&oq[obase + (size_t)tr * (NS * F4) + (size_t)k * F4], o);
            }
        }
    }
}

extern "C" void kernel_launch(void* const* d_in, const int* in_sizes, int n_in,
                              void* d_out, int out_size) {
    const float* inp = (const float*)d_in[0];
    float* out       = (float*)d_out;
    dim3 grid(NIB, NCHUNK);   // 18 x 32 = 576 blocks
    laplace_kernel<<<grid, 128>>>(inp, out);
}

// round 5
// speedup vs baseline: 1.3517x; 1.3517x over previous
#include <cuda_runtime.h>
#include <cuda_bf16.h>
#include <math.h>

// Laplace diagonal recurrence:
//   out[t, i, f] = e[i] * out[t-1, i, f] + decay[i] * inp[t, f]
// T = 2048, N_S = 108, F = 256, fp32.
//
// R5: R3 config (288 blocks, CHUNK=128, WARM=64, PF=8, GI=6, scaled
// recurrence) with a dieted warp-step: packed f32x2 FMA/MUL (halves math
// instruction count), immediate-offset stores with a single running
// pointer, plain STG.

constexpr int T_LEN  = 2048;
constexpr int F      = 256;
constexpr int NS     = 108;
constexpr int CHUNK  = 128;
constexpr int WARM   = 64;
constexpr int NCHUNK = T_LEN / CHUNK;   // 16
constexpr int GI     = 6;               // i-values per block
constexpr int NIB    = NS / GI;         // 18
constexpr int PF     = 8;               // prefetch depth (rows)
constexpr int F4     = F / 4;           // 64 float4 lanes per row

typedef unsigned long long u64;

__device__ __forceinline__ u64 fma2(u64 a, u64 b, u64 c) {
    u64 d;
    asm("fma.rn.f32x2 %0, %1, %2, %3;" : "=l"(d) : "l"(a), "l"(b), "l"(c));
    return d;
}
__device__ __forceinline__ u64 mul2(u64 a, u64 b) {
    u64 d;
    asm("mul.rn.f32x2 %0, %1, %2;" : "=l"(d) : "l"(a), "l"(b));
    return d;
}
__device__ __forceinline__ u64 pack2(float lo, float hi) {
    u64 d;
    asm("mov.b64 %0, {%1, %2};" : "=l"(d) : "f"(lo), "f"(hi));
    return d;
}

union V4 {
    float4 f;
    u64    u[2];
};

__global__ __launch_bounds__(128)
void laplace_kernel(const float* __restrict__ inp, float* __restrict__ out) {
    const int tid = threadIdx.x;
    const int fq  = tid & 63;        // float4 lane: f = 4*fq
    const int iq  = tid >> 6;        // 0..1 -> which half of the 6 i's
    const int ib  = blockIdx.x;      // 0..17
    const int chunk = blockIdx.y;    // 0..15

    // Per-i constants in double precision (matches reference ~1e-7).
    u64 e2[3], d2[3];
    const double c = pow(20.0, 1.0 / 99.0) - 1.0;
    #pragma unroll
    for (int k = 0; k < 3; k++) {
        int i = ib * GI + iq * 3 + k;
        double tau = pow(1.0 + c, (double)(i - 4));
        double s   = 4.0 / tau;
        double ed  = exp(-s);
        float ef = (float)ed;
        float df = (float)((1.0 - ed) / s);
        e2[k] = pack2(ef, ef);
        d2[k] = pack2(df, df);
    }

    const int t_start = chunk * CHUNK;
    const int warm    = (t_start < WARM) ? t_start : WARM;  // 0 or 64
    const int t0      = t_start - warm;
    const int steps   = warm + CHUNK;                        // 128 or 192

    const float4* __restrict__ ip = reinterpret_cast<const float4*>(inp)
                                    + (size_t)t0 * F4 + fq;

    // Scaled states: st' = e*st' + x;  out = dcy * st'.  2x f32x2 per state.
    u64 st[3][2];
    #pragma unroll
    for (int k = 0; k < 3; k++) { st[k][0] = 0ull; st[k][1] = 0ull; }

    // Prime the register pipeline.
    V4 pf[PF];
    #pragma unroll
    for (int j = 0; j < PF; j++) pf[j].f = __ldg(ip + j * F4);

    // ---- warm-up (no stores), warm is 0 or 64, divisible by PF ----
    for (int tb = 0; tb < warm; tb += PF) {
        #pragma unroll
        for (int j = 0; j < PF; j++) {
            const int t  = tb + j;
            const u64 x0 = pf[j].u[0];
            const u64 x1 = pf[j].u[1];
            const int tn = t + PF;
            if (tn < steps) pf[j].f = __ldg(ip + (size_t)tn * F4);
            #pragma unroll
            for (int k = 0; k < 3; k++) {
                st[k][0] = fma2(e2[k], st[k][0], x0);
                st[k][1] = fma2(e2[k], st[k][1], x1);
            }
        }
    }

    // ---- main: CHUNK=128 stored rows ----
    // out float4 index: ((t_start+t)*NS + i)*F4 + fq ; k stride = F4 = 64.
    float4* op = reinterpret_cast<float4*>(out)
               + ((size_t)t_start * NS + (size_t)(ib * GI + iq * 3)) * F4 + fq;
    for (int tb = 0; tb < CHUNK; tb += PF) {
        #pragma unroll
        for (int j = 0; j < PF; j++) {
            const int t  = warm + tb + j;
            const u64 x0 = pf[j].u[0];
            const u64 x1 = pf[j].u[1];
            const int tn = t + PF;
            if (tn < steps) pf[j].f = __ldg(ip + (size_t)tn * F4);
            #pragma unroll
            for (int k = 0; k < 3; k++) {
                st[k][0] = fma2(e2[k], st[k][0], x0);
                st[k][1] = fma2(e2[k], st[k][1], x1);
                V4 o;
                o.u[0] = mul2(d2[k], st[k][0]);
                o.u[1] = mul2(d2[k], st[k][1]);
                op[k * F4] = o.f;   // immediate offsets 0, 1024B, 2048B
            }
            op += NS * F4;
        }
    }
}

extern "C" void kernel_launch(void* const* d_in, const int* in_sizes, int n_in,
                              void* d_out, int out_size) {
    const float* inp = (const float*)d_in[0];
    float* out       = (float*)d_out;
    dim3 grid(NIB, NCHUNK);   // 18 x 16 = 288 blocks
    laplace_kernel<<<grid, 128>>>(inp, out);
}